// round 13
// baseline (speedup 1.0000x reference)
#include <cuda_runtime.h>

// ----------------------------------------------------------------------------
// Complex Daubechies wavelet forward decomposition, 6 levels. Round 13:
//  - R11 serial 5-launch chain (proven best structure) with TC widened to 64:
//    * half the blocks per level, halo read-amp 1.27 -> 1.20
//    * phase B: 4 columns/thread, float4 detail stores (STG.128), W-lo and
//      W-hi halves processed sequentially to cap registers (<=51, 5 blk/SM)
//  - FFMA-immediate coefficients, W-conv in regs -> smem -> H-conv,
//    details via __stcs, LL scratch L2-resident, L0 input via __ldcs.
// ----------------------------------------------------------------------------

#define C_LR0 (-0.046875f)
#define C_LR1 ( 0.078125f)
#define C_LR2 ( 0.46875f)
#define C_LI0 (-0.0605153648f)
#define C_LI1 (-0.0605153648f)
#define C_LI2 ( 0.1210307296f)
#define C_HR0 (-0.046875f)
#define C_HR1 (-0.078125f)
#define C_HR2 ( 0.46875f)
#define C_HI0 ( 0.0605153648f)
#define C_HI1 (-0.0605153648f)
#define C_HI2 (-0.1210307296f)

#define DECL_COEFS \
    const float KLR[3] = {C_LR0, C_LR1, C_LR2}; \
    const float KLI[3] = {C_LI0, C_LI1, C_LI2}; \
    const float KHR[3] = {C_HR0, C_HR1, C_HR2}; \
    const float KHI[3] = {C_HI0, C_HI1, C_HI2};

// Ping-pong scratch for the LL chain.
__device__ float g_scr0[32u * 2u * 512u * 512u];
__device__ float g_scr1[32u * 2u * 512u * 512u];

// Tile constants: TR=16, TC=64, 36 intermediate rows, pitch 68.
#define TRW 16
#define TCW 64
#define RIW 36
#define PW  68

// --------- shared phase-B body: 4 cols/thread, float4 stores ----------------
template<int H>
__device__ __forceinline__ void phaseB(
    const float* S0, const float* S1, const float* S2, const float* S3,
    float* __restrict__ out, float* __restrict__ nxt,
    int img, int r0, int c0, int tid)
{
    DECL_COEFS
    constexpr int half = H / 2;
    float* o_re = out + (long)img * (2l * 1024 * 1024);
    float* o_im = o_re + 1024 * 1024;
    float* n_re = nxt + (long)img * 2l * half * half;
    float* n_im = n_re + (long)half * half;

    const int r  = tid >> 4;        // 16 rows
    const int cg = tid & 15;        // 16 groups of 4 columns
    const int c4 = 4 * cg;
    const int rl = r0 + r, rh = rl + half;
    const int cl = c0 + c4, ch = cl + half;

    #pragma unroll 1
    for (int s = 0; s < 2; s++) {
        const float* A = s ? S2 : S0;   // W-filtered re
        const float* B = s ? S3 : S1;   // W-filtered im
        float lr0=0, lr1=0, lr2=0, lr3=0;   // H-lo re (LL or LH)
        float li0=0, li1=0, li2=0, li3=0;   // H-lo im
        float hr0=0, hr1=0, hr2=0, hr3=0;   // H-hi re (HL or HH)
        float hi0=0, hi1=0, hi2=0, hi3=0;   // H-hi im
        #pragma unroll
        for (int t = 0; t < 3; t++) {
            int ra = (2 * r + t) * PW + c4;
            int rb = (2 * r + 5 - t) * PW + c4;
            float4 xt = *(const float4*)&A[ra];
            float4 xs = *(const float4*)&A[rb];
            float4 yt = *(const float4*)&B[ra];
            float4 ys = *(const float4*)&B[rb];
            float p, m, q, n;
            p = xt.x + xs.x; m = xt.x - xs.x; q = yt.x + ys.x; n = yt.x - ys.x;
            lr0 += KLR[t]*p;  lr0 -= KLI[t]*q;
            li0 += KLI[t]*p;  li0 += KLR[t]*q;
            hr0 += KHR[t]*m;  hr0 -= KHI[t]*n;
            hi0 += KHI[t]*m;  hi0 += KHR[t]*n;
            p = xt.y + xs.y; m = xt.y - xs.y; q = yt.y + ys.y; n = yt.y - ys.y;
            lr1 += KLR[t]*p;  lr1 -= KLI[t]*q;
            li1 += KLI[t]*p;  li1 += KLR[t]*q;
            hr1 += KHR[t]*m;  hr1 -= KHI[t]*n;
            hi1 += KHI[t]*m;  hi1 += KHR[t]*n;
            p = xt.z + xs.z; m = xt.z - xs.z; q = yt.z + ys.z; n = yt.z - ys.z;
            lr2 += KLR[t]*p;  lr2 -= KLI[t]*q;
            li2 += KLI[t]*p;  li2 += KLR[t]*q;
            hr2 += KHR[t]*m;  hr2 -= KHI[t]*n;
            hi2 += KHI[t]*m;  hi2 += KHR[t]*n;
            p = xt.w + xs.w; m = xt.w - xs.w; q = yt.w + ys.w; n = yt.w - ys.w;
            lr3 += KLR[t]*p;  lr3 -= KLI[t]*q;
            li3 += KLI[t]*p;  li3 += KLR[t]*q;
            hr3 += KHR[t]*m;  hr3 -= KHI[t]*n;
            hi3 += KHI[t]*m;  hi3 += KHR[t]*n;
        }
        float4 lre = make_float4(lr0, lr1, lr2, lr3);
        float4 lim = make_float4(li0, li1, li2, li3);
        float4 hre = make_float4(hr0, hr1, hr2, hr3);
        float4 him = make_float4(hi0, hi1, hi2, hi3);
        if (s == 0) {
            // LL -> scratch; HL -> out (rh, cl)
            *(float4*)(n_re + (long)rl * half + cl) = lre;
            *(float4*)(n_im + (long)rl * half + cl) = lim;
            __stcs((float4*)(o_re + (long)rh * 1024 + cl), hre);
            __stcs((float4*)(o_im + (long)rh * 1024 + cl), him);
        } else {
            // LH -> out (rl, ch); HH -> out (rh, ch)
            __stcs((float4*)(o_re + (long)rl * 1024 + ch), lre);
            __stcs((float4*)(o_im + (long)rl * 1024 + ch), lim);
            __stcs((float4*)(o_re + (long)rh * 1024 + ch), hre);
            __stcs((float4*)(o_im + (long)rh * 1024 + ch), him);
        }
    }
}

// ======================= level-0 kernel (no imag input) =====================
__global__ void __launch_bounds__(256, 5)
wave0(const float* __restrict__ in, float* __restrict__ out,
      float* __restrict__ nxt)
{
    DECL_COEFS
    constexpr int H = 1024, hm = H - 1;
    __shared__ __align__(16) float S0[RIW * PW];
    __shared__ __align__(16) float S1[RIW * PW];
    __shared__ __align__(16) float S2[RIW * PW];
    __shared__ __align__(16) float S3[RIW * PW];

    const int tid = threadIdx.x;
    const int img = blockIdx.z;
    const int r0  = blockIdx.y * TRW;
    const int c0  = blockIdx.x * TCW;

    const float* in_re = in + (long)img * (1024l * 1024);

    const int gr0  = 2 * r0 - 3;
    const int gcal = 2 * c0 - 4;
    // 8 intermediate cols per item: items = 36 * (64/8) = 288
    for (int idx = tid; idx < RIW * (TCW / 8); idx += 256) {
        int ri = idx >> 3;
        int j  = idx & 7;
        int gr = (gr0 + ri) & hm;
        const float* pr = in_re + (long)gr * H;
        float x[24];
        #pragma unroll
        for (int k = 0; k < 6; k++) {
            int gc = (gcal + 16 * j + 4 * k) & hm;
            float4 v = __ldcs((const float4*)(pr + gc));
            x[4*k] = v.x; x[4*k+1] = v.y; x[4*k+2] = v.z; x[4*k+3] = v.w;
        }
        int o = ri * PW + 8 * j;
        #pragma unroll
        for (int hh = 0; hh < 2; hh++) {
            float lre[4], lim[4], hre[4], him[4];
            #pragma unroll
            for (int c = 0; c < 4; c++) {
                int cc = c + 4 * hh;
                float a = 0.f, b = 0.f, d = 0.f, e = 0.f;
                #pragma unroll
                for (int t = 0; t < 3; t++) {
                    float xt = x[2*cc + 1 + t], xs = x[2*cc + 6 - t];
                    float p = xt + xs, m = xt - xs;
                    a += KLR[t] * p;  b += KLI[t] * p;
                    d += KHR[t] * m;  e += KHI[t] * m;
                }
                lre[c] = a; lim[c] = b; hre[c] = d; him[c] = e;
            }
            int oo = o + 4 * hh;
            *(float4*)&S0[oo] = make_float4(lre[0], lre[1], lre[2], lre[3]);
            *(float4*)&S1[oo] = make_float4(lim[0], lim[1], lim[2], lim[3]);
            *(float4*)&S2[oo] = make_float4(hre[0], hre[1], hre[2], hre[3]);
            *(float4*)&S3[oo] = make_float4(him[0], him[1], him[2], him[3]);
        }
    }
    __syncthreads();
    phaseB<1024>(S0, S1, S2, S3, out, nxt, img, r0, c0, tid);
}

// ===================== levels 1..3 kernel (complex input) ===================
template<int H>
__global__ void __launch_bounds__(256, 5)
wave(const float* __restrict__ in, float* __restrict__ out,
     float* __restrict__ nxt)
{
    DECL_COEFS
    constexpr int hm = H - 1;
    __shared__ __align__(16) float S0[RIW * PW];
    __shared__ __align__(16) float S1[RIW * PW];
    __shared__ __align__(16) float S2[RIW * PW];
    __shared__ __align__(16) float S3[RIW * PW];

    const int tid = threadIdx.x;
    const int img = blockIdx.z;
    const int r0  = blockIdx.y * TRW;
    const int c0  = blockIdx.x * TCW;

    const float* in_re = in + (long)img * (2l * H * H);
    const float* in_im = in_re + (long)H * H;

    const int gr0  = 2 * r0 - 3;
    const int gcal = 2 * c0 - 4;
    // 4 intermediate cols per item: items = 36 * 16 = 576
    for (int idx = tid; idx < RIW * (TCW / 4); idx += 256) {
        int ri = idx >> 4;
        int j  = idx & 15;
        int gr = (gr0 + ri) & hm;
        const float* pr = in_re + (long)gr * H;
        const float* pi = in_im + (long)gr * H;
        float x[16], y[16];
        #pragma unroll
        for (int k = 0; k < 4; k++) {
            int gc = (gcal + 8 * j + 4 * k) & hm;
            float4 v = *(const float4*)(pr + gc);
            x[4*k] = v.x; x[4*k+1] = v.y; x[4*k+2] = v.z; x[4*k+3] = v.w;
            float4 w = *(const float4*)(pi + gc);
            y[4*k] = w.x; y[4*k+1] = w.y; y[4*k+2] = w.z; y[4*k+3] = w.w;
        }
        float lre[4], lim[4], hre[4], him[4];
        #pragma unroll
        for (int c = 0; c < 4; c++) {
            float a = 0.f, b = 0.f, d = 0.f, e = 0.f;
            #pragma unroll
            for (int t = 0; t < 3; t++) {
                float xt = x[2*c + 1 + t], xs = x[2*c + 6 - t];
                float p = xt + xs, m = xt - xs;
                a += KLR[t] * p;  b += KLI[t] * p;
                d += KHR[t] * m;  e += KHI[t] * m;
                float yt = y[2*c + 1 + t], ys = y[2*c + 6 - t];
                float q = yt + ys, n = yt - ys;
                a -= KLI[t] * q;  b += KLR[t] * q;
                d -= KHI[t] * n;  e += KHR[t] * n;
            }
            lre[c] = a; lim[c] = b; hre[c] = d; him[c] = e;
        }
        int o = ri * PW + 4 * j;
        *(float4*)&S0[o] = make_float4(lre[0], lre[1], lre[2], lre[3]);
        *(float4*)&S1[o] = make_float4(lim[0], lim[1], lim[2], lim[3]);
        *(float4*)&S2[o] = make_float4(hre[0], hre[1], hre[2], hre[3]);
        *(float4*)&S3[o] = make_float4(him[0], him[1], him[2], him[3]);
    }
    __syncthreads();
    phaseB<H>(S0, S1, S2, S3, out, nxt, img, r0, c0, tid);
}

// =============================== levels 4..5 ================================
__device__ __forceinline__ void tail_level(
    const float* sre, const float* sim, int ps,
    float* dre, float* dim, int pd,
    float* I0, float* I1, float* I2, float* I3,
    float* o_re, float* o_im, int h, bool last, int tid)
{
    DECL_COEFS
    const int hm = h - 1, W = h + 5, half = h >> 1;
    for (int s0 = 0; s0 < half; s0 += 8) {
        for (int idx = tid; idx < 8 * W; idx += 512) {
            int rr = idx / W, jx = idx - rr * W;
            int col = (jx - 3) & hm;
            int r2 = 2 * (s0 + rr) - 3;
            float aLr = 0, aLi = 0, aHr = 0, aHi = 0;
            #pragma unroll
            for (int t = 0; t < 3; t++) {
                int ra = (r2 + t) & hm, rb = (r2 + 5 - t) & hm;
                float xa = sre[ra * ps + col], xb = sre[rb * ps + col];
                float va = sim[ra * ps + col], vb = sim[rb * ps + col];
                float p = xa + xb, m = xa - xb, q = va + vb, n = va - vb;
                aLr += KLR[t]*p;  aLr -= KLI[t]*q;
                aLi += KLI[t]*p;  aLi += KLR[t]*q;
                aHr += KHR[t]*m;  aHr -= KHI[t]*n;
                aHi += KHI[t]*m;  aHi += KHR[t]*n;
            }
            I0[rr * 136 + jx] = aLr; I1[rr * 136 + jx] = aLi;
            I2[rr * 136 + jx] = aHr; I3[rr * 136 + jx] = aHi;
        }
        __syncthreads();
        for (int idx = tid; idx < 8 * half; idx += 512) {
            int rr = idx / half, c = idx - rr * half;
            int r = s0 + rr;
            float LLr = 0, LLi = 0, LHr = 0, LHi = 0;
            float HLr = 0, HLi = 0, HHr = 0, HHi = 0;
            #pragma unroll
            for (int t = 0; t < 3; t++) {
                int j0 = 2 * c + t, j1 = 2 * c + 5 - t;
                float ar = I0[rr * 136 + j0], br = I0[rr * 136 + j1];
                float ai = I1[rr * 136 + j0], bi = I1[rr * 136 + j1];
                float p = ar + br, m = ar - br, q = ai + bi, n = ai - bi;
                LLr += KLR[t]*p;  LLr -= KLI[t]*q;
                LLi += KLI[t]*p;  LLi += KLR[t]*q;
                LHr += KHR[t]*m;  LHr -= KHI[t]*n;
                LHi += KHI[t]*m;  LHi += KHR[t]*n;
                ar = I2[rr * 136 + j0]; br = I2[rr * 136 + j1];
                ai = I3[rr * 136 + j0]; bi = I3[rr * 136 + j1];
                p = ar + br; m = ar - br; q = ai + bi; n = ai - bi;
                HLr += KLR[t]*p;  HLr -= KLI[t]*q;
                HLi += KLI[t]*p;  HLi += KLR[t]*q;
                HHr += KHR[t]*m;  HHr -= KHI[t]*n;
                HHi += KHI[t]*m;  HHi += KHR[t]*n;
            }
            o_re[r * 1024 + c + half]          = LHr;
            o_im[r * 1024 + c + half]          = LHi;
            o_re[(r + half) * 1024 + c]        = HLr;
            o_im[(r + half) * 1024 + c]        = HLi;
            o_re[(r + half) * 1024 + c + half] = HHr;
            o_im[(r + half) * 1024 + c + half] = HHi;
            if (last) {
                o_re[r * 1024 + c] = LLr;
                o_im[r * 1024 + c] = LLi;
            } else {
                dre[r * pd + c] = LLr;
                dim[r * pd + c] = LLi;
            }
        }
        __syncthreads();
    }
}

__global__ void __launch_bounds__(512)
wave_tail45(const float* __restrict__ in, float* __restrict__ out)
{
    extern __shared__ float sm[];
    constexpr int AP = 68, BP = 36;
    float* A_re = sm;
    float* A_im = A_re + 64 * AP;
    float* B_re = A_im + 64 * AP;
    float* B_im = B_re + 32 * BP;
    float* I0   = B_im + 32 * BP;
    float* I1   = I0 + 8 * 136;
    float* I2   = I1 + 8 * 136;
    float* I3   = I2 + 8 * 136;

    const int tid = threadIdx.x;
    const int img = blockIdx.x;

    const float* g_re = in + (long)img * 2l * 64 * 64;
    const float* g_im = g_re + 64 * 64;
    for (int idx = tid; idx < 64 * 16; idx += 512) {
        int rr = idx >> 4, c4 = (idx & 15) * 4;
        *(float4*)&A_re[rr * AP + c4] = *(const float4*)(g_re + rr * 64 + c4);
        *(float4*)&A_im[rr * AP + c4] = *(const float4*)(g_im + rr * 64 + c4);
    }
    __syncthreads();

    float* o_re = out + (long)img * 2l * 1024 * 1024;
    float* o_im = o_re + 1024 * 1024;

    tail_level(A_re, A_im, AP, B_re, B_im, BP, I0, I1, I2, I3,
               o_re, o_im, 64, false, tid);
    tail_level(B_re, B_im, BP, nullptr, nullptr, 0, I0, I1, I2, I3,
               o_re, o_im, 32, true, tid);
}

// ================================= launch ===================================
extern "C" void kernel_launch(void* const* d_in, const int* in_sizes, int n_in,
                              void* d_out, int out_size) {
    const float* images = (const float*)d_in[0];
    float* out = (float*)d_out;

    float *scr0 = nullptr, *scr1 = nullptr;
    cudaGetSymbolAddress((void**)&scr0, g_scr0);
    cudaGetSymbolAddress((void**)&scr1, g_scr1);

    const int bc = in_sizes[0] / (1024 * 1024);  // B*C = 24

    constexpr size_t SMT = (size_t)(2 * 64 * 68 + 2 * 32 * 36 + 4 * 8 * 136) * 4;
    cudaFuncSetAttribute(wave_tail45,
                         cudaFuncAttributeMaxDynamicSharedMemorySize, SMT);

    dim3 blk(256);
    // Level 0: h=1024 (imag identically zero)
    {
        dim3 grid(512 / TCW, 512 / TRW, bc);
        wave0<<<grid, blk>>>(images, out, scr0);
    }
    // Level 1: h=512
    {
        dim3 grid(256 / TCW, 256 / TRW, bc);
        wave<512><<<grid, blk>>>(scr0, out, scr1);
    }
    // Level 2: h=256
    {
        dim3 grid(128 / TCW, 128 / TRW, bc);
        wave<256><<<grid, blk>>>(scr1, out, scr0);
    }
    // Level 3: h=128
    {
        dim3 grid(64 / TCW, 64 / TRW, bc);
        wave<128><<<grid, blk>>>(scr0, out, scr1);
    }
    // Levels 4..5 fused, one block per image
    wave_tail45<<<bc, 512, SMT>>>(scr1, out);
}

// round 15
// speedup vs baseline: 1.1339x; 1.1339x over previous
#include <cuda_runtime.h>

// ----------------------------------------------------------------------------
// Complex Daubechies wavelet forward decomposition, 6 levels. Round 15:
//  - Round-14 structure with the tile-count bug fixed (L2: 32 tiles/img,
//    L3: 8 tiles/img — R14 used half these counts, leaving stale output).
//  - launch 1: R11 wave0 (level 0) verbatim.
//  - launch 2: persistent kernel L1 -> L2 -> L3 -> tail(L4..5) with software
//    grid barriers; bodies are the constexpr-specialized R11/R12 pieces.
// ----------------------------------------------------------------------------

#define C_LR0 (-0.046875f)
#define C_LR1 ( 0.078125f)
#define C_LR2 ( 0.46875f)
#define C_LI0 (-0.0605153648f)
#define C_LI1 (-0.0605153648f)
#define C_LI2 ( 0.1210307296f)
#define C_HR0 (-0.046875f)
#define C_HR1 (-0.078125f)
#define C_HR2 ( 0.46875f)
#define C_HI0 ( 0.0605153648f)
#define C_HI1 (-0.0605153648f)
#define C_HI2 (-0.1210307296f)

#define DECL_COEFS \
    const float KLR[3] = {C_LR0, C_LR1, C_LR2}; \
    const float KLI[3] = {C_LI0, C_LI1, C_LI2}; \
    const float KHR[3] = {C_HR0, C_HR1, C_HR2}; \
    const float KHI[3] = {C_HI0, C_HI1, C_HI2};

// Per-level scratch (disjoint).
__device__ float g_s01[24u * 2u * 512u * 512u];
__device__ float g_s12[24u * 2u * 256u * 256u];
__device__ float g_s23[24u * 2u * 128u * 128u];
__device__ float g_s34[24u * 2u * 64u * 64u];

// Grid-barrier state (generation scheme; safe across graph replays).
__device__ unsigned g_count = 0;
__device__ unsigned g_gen   = 0;

__device__ __forceinline__ void grid_barrier(unsigned nb) {
    __threadfence();
    __syncthreads();
    if (threadIdx.x == 0) {
        volatile unsigned* vgen = &g_gen;
        unsigned g = *vgen;
        unsigned old = atomicAdd(&g_count, 1);
        if (old == nb - 1) {
            g_count = 0;
            __threadfence();
            *vgen = g + 1;
        } else {
            while (*vgen == g) { }
        }
    }
    __syncthreads();
}

#define TRW 16
#define TCW 32
#define RIW 36
#define PW  36
#define SARR 1296

// --------- shared phase-B body (R11 verbatim) -------------------------------
template<int H>
__device__ __forceinline__ void phaseB(
    const float* S0, const float* S1, const float* S2, const float* S3,
    float* __restrict__ out, float* __restrict__ nxt,
    int img, int r0, int c0, int tid)
{
    DECL_COEFS
    constexpr int half = H / 2;
    float* o_re = out + (long)img * (2l * 1024 * 1024);
    float* o_im = o_re + 1024 * 1024;
    float* n_re = nxt + (long)img * 2l * half * half;
    float* n_im = n_re + (long)half * half;

    int r  = tid >> 4;
    int cg = tid & 15;
    int c2 = 2 * cg;
    float LLr0=0, LLi0=0, LHr0=0, LHi0=0, HLr0=0, HLi0=0, HHr0=0, HHi0=0;
    float LLr1=0, LLi1=0, LHr1=0, LHi1=0, HLr1=0, HLi1=0, HHr1=0, HHi1=0;
    #pragma unroll
    for (int t = 0; t < 3; t++) {
        int ra = (2 * r + t) * PW + c2;
        int rb = (2 * r + 5 - t) * PW + c2;
        float2 art = *(const float2*)&S0[ra], ars = *(const float2*)&S0[rb];
        float2 ait = *(const float2*)&S1[ra], ais = *(const float2*)&S1[rb];
        float2 brt = *(const float2*)&S2[ra], brs = *(const float2*)&S2[rb];
        float2 bit = *(const float2*)&S3[ra], bis = *(const float2*)&S3[rb];
        {
            float p = art.x + ars.x, m = art.x - ars.x;
            float q = ait.x + ais.x, n = ait.x - ais.x;
            LLr0 += KLR[t]*p;  LLr0 -= KLI[t]*q;
            LLi0 += KLI[t]*p;  LLi0 += KLR[t]*q;
            HLr0 += KHR[t]*m;  HLr0 -= KHI[t]*n;
            HLi0 += KHI[t]*m;  HLi0 += KHR[t]*n;
            float p2 = brt.x + brs.x, m2 = brt.x - brs.x;
            float q2 = bit.x + bis.x, n2 = bit.x - bis.x;
            LHr0 += KLR[t]*p2; LHr0 -= KLI[t]*q2;
            LHi0 += KLI[t]*p2; LHi0 += KLR[t]*q2;
            HHr0 += KHR[t]*m2; HHr0 -= KHI[t]*n2;
            HHi0 += KHI[t]*m2; HHi0 += KHR[t]*n2;
        }
        {
            float p = art.y + ars.y, m = art.y - ars.y;
            float q = ait.y + ais.y, n = ait.y - ais.y;
            LLr1 += KLR[t]*p;  LLr1 -= KLI[t]*q;
            LLi1 += KLI[t]*p;  LLi1 += KLR[t]*q;
            HLr1 += KHR[t]*m;  HLr1 -= KHI[t]*n;
            HLi1 += KHI[t]*m;  HLi1 += KHR[t]*n;
            float p2 = brt.y + brs.y, m2 = brt.y - brs.y;
            float q2 = bit.y + bis.y, n2 = bit.y - bis.y;
            LHr1 += KLR[t]*p2; LHr1 -= KLI[t]*q2;
            LHi1 += KLI[t]*p2; LHi1 += KLR[t]*q2;
            HHr1 += KHR[t]*m2; HHr1 -= KHI[t]*n2;
            HHi1 += KHI[t]*m2; HHi1 += KHR[t]*n2;
        }
    }
    int rl = r0 + r, rh = rl + half;
    int cl = c0 + c2, ch = cl + half;
    *(float2*)(n_re + (long)rl * half + cl) = make_float2(LLr0, LLr1);
    *(float2*)(n_im + (long)rl * half + cl) = make_float2(LLi0, LLi1);
    __stcs((float2*)(o_re + (long)rl * 1024 + ch), make_float2(LHr0, LHr1));
    __stcs((float2*)(o_im + (long)rl * 1024 + ch), make_float2(LHi0, LHi1));
    __stcs((float2*)(o_re + (long)rh * 1024 + cl), make_float2(HLr0, HLr1));
    __stcs((float2*)(o_im + (long)rh * 1024 + cl), make_float2(HLi0, HLi1));
    __stcs((float2*)(o_re + (long)rh * 1024 + ch), make_float2(HHr0, HHr1));
    __stcs((float2*)(o_im + (long)rh * 1024 + ch), make_float2(HHi0, HHi1));
}

// ======================= level-0 kernel (R11 verbatim) ======================
__global__ void __launch_bounds__(256, 5)
wave0(const float* __restrict__ in, float* __restrict__ out,
      float* __restrict__ nxt)
{
    DECL_COEFS
    constexpr int H = 1024, hm = H - 1;
    __shared__ __align__(16) float S0[RIW * PW];
    __shared__ __align__(16) float S1[RIW * PW];
    __shared__ __align__(16) float S2[RIW * PW];
    __shared__ __align__(16) float S3[RIW * PW];

    const int tid = threadIdx.x;
    const int img = blockIdx.z;
    const int r0  = blockIdx.y * TRW;
    const int c0  = blockIdx.x * TCW;

    const float* in_re = in + (long)img * (1024l * 1024);
    const int gr0  = 2 * r0 - 3;
    const int gcal = 2 * c0 - 4;
    for (int idx = tid; idx < RIW * (TCW / 8); idx += 256) {
        int ri = idx >> 2;
        int j  = idx & 3;
        int gr = (gr0 + ri) & hm;
        const float* pr = in_re + (long)gr * H;
        float x[24];
        #pragma unroll
        for (int k = 0; k < 6; k++) {
            int gc = (gcal + 16 * j + 4 * k) & hm;
            float4 v = __ldcs((const float4*)(pr + gc));
            x[4*k] = v.x; x[4*k+1] = v.y; x[4*k+2] = v.z; x[4*k+3] = v.w;
        }
        int o = ri * PW + 8 * j;
        #pragma unroll
        for (int hh = 0; hh < 2; hh++) {
            float lre[4], lim[4], hre[4], him[4];
            #pragma unroll
            for (int c = 0; c < 4; c++) {
                int cc = c + 4 * hh;
                float a = 0.f, b = 0.f, d = 0.f, e = 0.f;
                #pragma unroll
                for (int t = 0; t < 3; t++) {
                    float xt = x[2*cc + 1 + t], xs = x[2*cc + 6 - t];
                    float p = xt + xs, m = xt - xs;
                    a += KLR[t] * p;  b += KLI[t] * p;
                    d += KHR[t] * m;  e += KHI[t] * m;
                }
                lre[c] = a; lim[c] = b; hre[c] = d; him[c] = e;
            }
            int oo = o + 4 * hh;
            *(float4*)&S0[oo] = make_float4(lre[0], lre[1], lre[2], lre[3]);
            *(float4*)&S1[oo] = make_float4(lim[0], lim[1], lim[2], lim[3]);
            *(float4*)&S2[oo] = make_float4(hre[0], hre[1], hre[2], hre[3]);
            *(float4*)&S3[oo] = make_float4(him[0], him[1], him[2], him[3]);
        }
    }
    __syncthreads();
    phaseB<1024>(S0, S1, S2, S3, out, nxt, img, r0, c0, tid);
}

// ----------------------- levels 1..3 piece (R12 verbatim) -------------------
template<int H>
__device__ __forceinline__ void wave_piece(
    int u, const float* __restrict__ in, float* __restrict__ out,
    float* __restrict__ nxt, float* S0, float* S1, float* S2, float* S3, int tid)
{
    DECL_COEFS
    constexpr int hm   = H - 1;
    constexpr int TX   = (H / 2) / TCW;
    constexpr int TPI  = TX * ((H / 2) / TRW);
    const int img = u / TPI;
    const int rem = u & (TPI - 1);
    const int by  = rem / TX;
    const int bx  = rem & (TX - 1);
    const int r0  = by * TRW, c0 = bx * TCW;

    const float* in_re = in + (long)img * (2l * H * H);
    const float* in_im = in_re + (long)H * H;

    const int gr0  = 2 * r0 - 3;
    const int gcal = 2 * c0 - 4;
    for (int idx = tid; idx < RIW * (TCW / 4); idx += 256) {
        int ri = idx >> 3;
        int j  = idx & 7;
        int gr = (gr0 + ri) & hm;
        const float* pr = in_re + (long)gr * H;
        const float* pi = in_im + (long)gr * H;
        float x[16], y[16];
        #pragma unroll
        for (int k = 0; k < 4; k++) {
            int gc = (gcal + 8 * j + 4 * k) & hm;
            float4 v = *(const float4*)(pr + gc);
            x[4*k] = v.x; x[4*k+1] = v.y; x[4*k+2] = v.z; x[4*k+3] = v.w;
            float4 w = *(const float4*)(pi + gc);
            y[4*k] = w.x; y[4*k+1] = w.y; y[4*k+2] = w.z; y[4*k+3] = w.w;
        }
        float lre[4], lim[4], hre[4], him[4];
        #pragma unroll
        for (int c = 0; c < 4; c++) {
            float a = 0.f, b = 0.f, d = 0.f, e = 0.f;
            #pragma unroll
            for (int t = 0; t < 3; t++) {
                float xt = x[2*c + 1 + t], xs = x[2*c + 6 - t];
                float p = xt + xs, m = xt - xs;
                a += KLR[t] * p;  b += KLI[t] * p;
                d += KHR[t] * m;  e += KHI[t] * m;
                float yt = y[2*c + 1 + t], ys = y[2*c + 6 - t];
                float q = yt + ys, n = yt - ys;
                a -= KLI[t] * q;  b += KLR[t] * q;
                d -= KHI[t] * n;  e += KHR[t] * n;
            }
            lre[c] = a; lim[c] = b; hre[c] = d; him[c] = e;
        }
        int o = ri * PW + 4 * j;
        *(float4*)&S0[o] = make_float4(lre[0], lre[1], lre[2], lre[3]);
        *(float4*)&S1[o] = make_float4(lim[0], lim[1], lim[2], lim[3]);
        *(float4*)&S2[o] = make_float4(hre[0], hre[1], hre[2], hre[3]);
        *(float4*)&S3[o] = make_float4(him[0], him[1], him[2], him[3]);
    }
    __syncthreads();
    phaseB<H>(S0, S1, S2, S3, out, nxt, img, r0, c0, tid);
    __syncthreads();   // smem reused by next tile
}

// -------------------------- tail (256-thread version) -----------------------
__device__ __forceinline__ void tail_level(
    const float* sre, const float* sim, int ps,
    float* dre, float* dim, int pd,
    float* I0, float* I1, float* I2, float* I3,
    float* o_re, float* o_im, int h, bool last, int tid)
{
    DECL_COEFS
    const int hm = h - 1, W = h + 5, half = h >> 1;
    for (int s0 = 0; s0 < half; s0 += 8) {
        for (int idx = tid; idx < 8 * W; idx += 256) {
            int rr = idx / W, jx = idx - rr * W;
            int col = (jx - 3) & hm;
            int r2 = 2 * (s0 + rr) - 3;
            float aLr = 0, aLi = 0, aHr = 0, aHi = 0;
            #pragma unroll
            for (int t = 0; t < 3; t++) {
                int ra = (r2 + t) & hm, rb = (r2 + 5 - t) & hm;
                float xa = sre[ra * ps + col], xb = sre[rb * ps + col];
                float va = sim[ra * ps + col], vb = sim[rb * ps + col];
                float p = xa + xb, m = xa - xb, q = va + vb, n = va - vb;
                aLr += KLR[t]*p;  aLr -= KLI[t]*q;
                aLi += KLI[t]*p;  aLi += KLR[t]*q;
                aHr += KHR[t]*m;  aHr -= KHI[t]*n;
                aHi += KHI[t]*m;  aHi += KHR[t]*n;
            }
            I0[rr * 136 + jx] = aLr; I1[rr * 136 + jx] = aLi;
            I2[rr * 136 + jx] = aHr; I3[rr * 136 + jx] = aHi;
        }
        __syncthreads();
        for (int idx = tid; idx < 8 * half; idx += 256) {
            int rr = idx / half, c = idx - rr * half;
            int r = s0 + rr;
            float LLr = 0, LLi = 0, LHr = 0, LHi = 0;
            float HLr = 0, HLi = 0, HHr = 0, HHi = 0;
            #pragma unroll
            for (int t = 0; t < 3; t++) {
                int j0 = 2 * c + t, j1 = 2 * c + 5 - t;
                float ar = I0[rr * 136 + j0], br = I0[rr * 136 + j1];
                float ai = I1[rr * 136 + j0], bi = I1[rr * 136 + j1];
                float p = ar + br, m = ar - br, q = ai + bi, n = ai - bi;
                LLr += KLR[t]*p;  LLr -= KLI[t]*q;
                LLi += KLI[t]*p;  LLi += KLR[t]*q;
                LHr += KHR[t]*m;  LHr -= KHI[t]*n;
                LHi += KHI[t]*m;  LHi += KHR[t]*n;
                ar = I2[rr * 136 + j0]; br = I2[rr * 136 + j1];
                ai = I3[rr * 136 + j0]; bi = I3[rr * 136 + j1];
                p = ar + br; m = ar - br; q = ai + bi; n = ai - bi;
                HLr += KLR[t]*p;  HLr -= KLI[t]*q;
                HLi += KLI[t]*p;  HLi += KLR[t]*q;
                HHr += KHR[t]*m;  HHr -= KHI[t]*n;
                HHi += KHI[t]*m;  HHi += KHR[t]*n;
            }
            o_re[r * 1024 + c + half]          = LHr;
            o_im[r * 1024 + c + half]          = LHi;
            o_re[(r + half) * 1024 + c]        = HLr;
            o_im[(r + half) * 1024 + c]        = HLi;
            o_re[(r + half) * 1024 + c + half] = HHr;
            o_im[(r + half) * 1024 + c + half] = HHi;
            if (last) {
                o_re[r * 1024 + c] = LLr;
                o_im[r * 1024 + c] = LLi;
            } else {
                dre[r * pd + c] = LLr;
                dim[r * pd + c] = LLi;
            }
        }
        __syncthreads();
    }
}

__device__ __forceinline__ void tail_unit(int img, const float* __restrict__ s34,
                                          float* __restrict__ out, float* sm, int tid)
{
    constexpr int AP = 68, BP = 36;
    float* A_re = sm;
    float* A_im = A_re + 64 * AP;
    float* B_re = A_im + 64 * AP;
    float* B_im = B_re + 32 * BP;
    float* I0   = B_im + 32 * BP;
    float* I1   = I0 + 8 * 136;
    float* I2   = I1 + 8 * 136;
    float* I3   = I2 + 8 * 136;

    const float* g_re = s34 + (long)img * 2l * 64 * 64;
    const float* g_im = g_re + 64 * 64;
    for (int idx = tid; idx < 64 * 16; idx += 256) {
        int rr = idx >> 4, c4 = (idx & 15) * 4;
        *(float4*)&A_re[rr * AP + c4] = *(const float4*)(g_re + rr * 64 + c4);
        *(float4*)&A_im[rr * AP + c4] = *(const float4*)(g_im + rr * 64 + c4);
    }
    __syncthreads();

    float* o_re = out + (long)img * 2l * 1024 * 1024;
    float* o_im = o_re + 1024 * 1024;

    tail_level(A_re, A_im, AP, B_re, B_im, BP, I0, I1, I2, I3,
               o_re, o_im, 64, false, tid);
    tail_level(B_re, B_im, BP, nullptr, nullptr, 0, I0, I1, I2, I3,
               o_re, o_im, 32, true, tid);
    __syncthreads();
}

// ---------------------- persistent kernel: L1..L5 ---------------------------
__global__ void __launch_bounds__(256)
persist_rest(float* __restrict__ out,
             float* __restrict__ s01, float* __restrict__ s12,
             float* __restrict__ s23, float* __restrict__ s34)
{
    extern __shared__ float sm[];
    float* S0 = sm;
    float* S1 = sm + SARR;
    float* S2 = sm + 2 * SARR;
    float* S3 = sm + 3 * SARR;

    const int tid = threadIdx.x;
    const unsigned NB = gridDim.x;

    // L1: 24 imgs x 128 tiles
    for (int u = blockIdx.x; u < 24 * 128; u += NB)
        wave_piece<512>(u, s01, out, s12, S0, S1, S2, S3, tid);
    grid_barrier(NB);
    // L2: 24 imgs x 32 tiles  (FIXED: was 24*16)
    for (int u = blockIdx.x; u < 24 * 32; u += NB)
        wave_piece<256>(u, s12, out, s23, S0, S1, S2, S3, tid);
    grid_barrier(NB);
    // L3: 24 imgs x 8 tiles   (FIXED: was 24*4)
    for (int u = blockIdx.x; u < 24 * 8; u += NB)
        wave_piece<128>(u, s23, out, s34, S0, S1, S2, S3, tid);
    grid_barrier(NB);
    // tail: 24 units
    for (int u = blockIdx.x; u < 24; u += NB)
        tail_unit(u, s34, out, sm, tid);
}

// ================================= launch ===================================
extern "C" void kernel_launch(void* const* d_in, const int* in_sizes, int n_in,
                              void* d_out, int out_size) {
    const float* images = (const float*)d_in[0];
    float* out = (float*)d_out;

    float *s01, *s12, *s23, *s34;
    cudaGetSymbolAddress((void**)&s01, g_s01);
    cudaGetSymbolAddress((void**)&s12, g_s12);
    cudaGetSymbolAddress((void**)&s23, g_s23);
    cudaGetSymbolAddress((void**)&s34, g_s34);

    const int bc = in_sizes[0] / (1024 * 1024);  // 24

    constexpr size_t SMEM = 15360u * 4u;   // 61,440 B (tail layout; wave 20.7KB)
    cudaFuncSetAttribute(persist_rest,
                         cudaFuncAttributeMaxDynamicSharedMemorySize, SMEM);

    int dev = 0;
    cudaGetDevice(&dev);
    int nsm = 148;
    cudaDeviceGetAttribute(&nsm, cudaDevAttrMultiProcessorCount, dev);
    int occ = 1;
    cudaOccupancyMaxActiveBlocksPerMultiprocessor(&occ, persist_rest, 256, SMEM);
    if (occ < 1) occ = 1;
    if (occ > 3) occ = 3;
    int nb = nsm * occ;

    // Level 0 (R11 kernel verbatim)
    {
        dim3 grid(512 / TCW, 512 / TRW, bc);
        wave0<<<grid, dim3(256)>>>(images, out, s01);
    }
    // Levels 1..5 in one persistent launch
    persist_rest<<<nb, 256, SMEM>>>(out, s01, s12, s23, s34);
}

// round 16
// speedup vs baseline: 1.1579x; 1.0212x over previous
#include <cuda_runtime.h>

// ----------------------------------------------------------------------------
// Complex Daubechies wavelet forward decomposition, 6 levels. Round 16:
//  - launch 1: R11 wave0 (level 0) verbatim.
//  - launch 2: persistent kernel L1 -> L2 -> L3 ONLY (20.7KB smem -> 5 blk/SM,
//    ~740 co-resident blocks vs R15's 456 which was capped by the tail's 61KB).
//  - launch 3: tail (levels 4..5), 24 blocks x 512 threads (proven ~8us).
// ----------------------------------------------------------------------------

#define C_LR0 (-0.046875f)
#define C_LR1 ( 0.078125f)
#define C_LR2 ( 0.46875f)
#define C_LI0 (-0.0605153648f)
#define C_LI1 (-0.0605153648f)
#define C_LI2 ( 0.1210307296f)
#define C_HR0 (-0.046875f)
#define C_HR1 (-0.078125f)
#define C_HR2 ( 0.46875f)
#define C_HI0 ( 0.0605153648f)
#define C_HI1 (-0.0605153648f)
#define C_HI2 (-0.1210307296f)

#define DECL_COEFS \
    const float KLR[3] = {C_LR0, C_LR1, C_LR2}; \
    const float KLI[3] = {C_LI0, C_LI1, C_LI2}; \
    const float KHR[3] = {C_HR0, C_HR1, C_HR2}; \
    const float KHI[3] = {C_HI0, C_HI1, C_HI2};

// Per-level scratch (disjoint).
__device__ float g_s01[24u * 2u * 512u * 512u];
__device__ float g_s12[24u * 2u * 256u * 256u];
__device__ float g_s23[24u * 2u * 128u * 128u];
__device__ float g_s34[24u * 2u * 64u * 64u];

// Grid-barrier state (generation scheme; safe across graph replays).
__device__ unsigned g_count = 0;
__device__ unsigned g_gen   = 0;

__device__ __forceinline__ void grid_barrier(unsigned nb) {
    __threadfence();
    __syncthreads();
    if (threadIdx.x == 0) {
        volatile unsigned* vgen = &g_gen;
        unsigned g = *vgen;
        unsigned old = atomicAdd(&g_count, 1);
        if (old == nb - 1) {
            g_count = 0;
            __threadfence();
            *vgen = g + 1;
        } else {
            while (*vgen == g) { }
        }
    }
    __syncthreads();
}

#define TRW 16
#define TCW 32
#define RIW 36
#define PW  36
#define SARR 1296

// --------- shared phase-B body (R11 verbatim) -------------------------------
template<int H>
__device__ __forceinline__ void phaseB(
    const float* S0, const float* S1, const float* S2, const float* S3,
    float* __restrict__ out, float* __restrict__ nxt,
    int img, int r0, int c0, int tid)
{
    DECL_COEFS
    constexpr int half = H / 2;
    float* o_re = out + (long)img * (2l * 1024 * 1024);
    float* o_im = o_re + 1024 * 1024;
    float* n_re = nxt + (long)img * 2l * half * half;
    float* n_im = n_re + (long)half * half;

    int r  = tid >> 4;
    int cg = tid & 15;
    int c2 = 2 * cg;
    float LLr0=0, LLi0=0, LHr0=0, LHi0=0, HLr0=0, HLi0=0, HHr0=0, HHi0=0;
    float LLr1=0, LLi1=0, LHr1=0, LHi1=0, HLr1=0, HLi1=0, HHr1=0, HHi1=0;
    #pragma unroll
    for (int t = 0; t < 3; t++) {
        int ra = (2 * r + t) * PW + c2;
        int rb = (2 * r + 5 - t) * PW + c2;
        float2 art = *(const float2*)&S0[ra], ars = *(const float2*)&S0[rb];
        float2 ait = *(const float2*)&S1[ra], ais = *(const float2*)&S1[rb];
        float2 brt = *(const float2*)&S2[ra], brs = *(const float2*)&S2[rb];
        float2 bit = *(const float2*)&S3[ra], bis = *(const float2*)&S3[rb];
        {
            float p = art.x + ars.x, m = art.x - ars.x;
            float q = ait.x + ais.x, n = ait.x - ais.x;
            LLr0 += KLR[t]*p;  LLr0 -= KLI[t]*q;
            LLi0 += KLI[t]*p;  LLi0 += KLR[t]*q;
            HLr0 += KHR[t]*m;  HLr0 -= KHI[t]*n;
            HLi0 += KHI[t]*m;  HLi0 += KHR[t]*n;
            float p2 = brt.x + brs.x, m2 = brt.x - brs.x;
            float q2 = bit.x + bis.x, n2 = bit.x - bis.x;
            LHr0 += KLR[t]*p2; LHr0 -= KLI[t]*q2;
            LHi0 += KLI[t]*p2; LHi0 += KLR[t]*q2;
            HHr0 += KHR[t]*m2; HHr0 -= KHI[t]*n2;
            HHi0 += KHI[t]*m2; HHi0 += KHR[t]*n2;
        }
        {
            float p = art.y + ars.y, m = art.y - ars.y;
            float q = ait.y + ais.y, n = ait.y - ais.y;
            LLr1 += KLR[t]*p;  LLr1 -= KLI[t]*q;
            LLi1 += KLI[t]*p;  LLi1 += KLR[t]*q;
            HLr1 += KHR[t]*m;  HLr1 -= KHI[t]*n;
            HLi1 += KHI[t]*m;  HLi1 += KHR[t]*n;
            float p2 = brt.y + brs.y, m2 = brt.y - brs.y;
            float q2 = bit.y + bis.y, n2 = bit.y - bis.y;
            LHr1 += KLR[t]*p2; LHr1 -= KLI[t]*q2;
            LHi1 += KLI[t]*p2; LHi1 += KLR[t]*q2;
            HHr1 += KHR[t]*m2; HHr1 -= KHI[t]*n2;
            HHi1 += KHI[t]*m2; HHi1 += KHR[t]*n2;
        }
    }
    int rl = r0 + r, rh = rl + half;
    int cl = c0 + c2, ch = cl + half;
    *(float2*)(n_re + (long)rl * half + cl) = make_float2(LLr0, LLr1);
    *(float2*)(n_im + (long)rl * half + cl) = make_float2(LLi0, LLi1);
    __stcs((float2*)(o_re + (long)rl * 1024 + ch), make_float2(LHr0, LHr1));
    __stcs((float2*)(o_im + (long)rl * 1024 + ch), make_float2(LHi0, LHi1));
    __stcs((float2*)(o_re + (long)rh * 1024 + cl), make_float2(HLr0, HLr1));
    __stcs((float2*)(o_im + (long)rh * 1024 + cl), make_float2(HLi0, HLi1));
    __stcs((float2*)(o_re + (long)rh * 1024 + ch), make_float2(HHr0, HHr1));
    __stcs((float2*)(o_im + (long)rh * 1024 + ch), make_float2(HHi0, HHi1));
}

// ======================= level-0 kernel (R11 verbatim) ======================
__global__ void __launch_bounds__(256, 5)
wave0(const float* __restrict__ in, float* __restrict__ out,
      float* __restrict__ nxt)
{
    DECL_COEFS
    constexpr int H = 1024, hm = H - 1;
    __shared__ __align__(16) float S0[RIW * PW];
    __shared__ __align__(16) float S1[RIW * PW];
    __shared__ __align__(16) float S2[RIW * PW];
    __shared__ __align__(16) float S3[RIW * PW];

    const int tid = threadIdx.x;
    const int img = blockIdx.z;
    const int r0  = blockIdx.y * TRW;
    const int c0  = blockIdx.x * TCW;

    const float* in_re = in + (long)img * (1024l * 1024);
    const int gr0  = 2 * r0 - 3;
    const int gcal = 2 * c0 - 4;
    for (int idx = tid; idx < RIW * (TCW / 8); idx += 256) {
        int ri = idx >> 2;
        int j  = idx & 3;
        int gr = (gr0 + ri) & hm;
        const float* pr = in_re + (long)gr * H;
        float x[24];
        #pragma unroll
        for (int k = 0; k < 6; k++) {
            int gc = (gcal + 16 * j + 4 * k) & hm;
            float4 v = __ldcs((const float4*)(pr + gc));
            x[4*k] = v.x; x[4*k+1] = v.y; x[4*k+2] = v.z; x[4*k+3] = v.w;
        }
        int o = ri * PW + 8 * j;
        #pragma unroll
        for (int hh = 0; hh < 2; hh++) {
            float lre[4], lim[4], hre[4], him[4];
            #pragma unroll
            for (int c = 0; c < 4; c++) {
                int cc = c + 4 * hh;
                float a = 0.f, b = 0.f, d = 0.f, e = 0.f;
                #pragma unroll
                for (int t = 0; t < 3; t++) {
                    float xt = x[2*cc + 1 + t], xs = x[2*cc + 6 - t];
                    float p = xt + xs, m = xt - xs;
                    a += KLR[t] * p;  b += KLI[t] * p;
                    d += KHR[t] * m;  e += KHI[t] * m;
                }
                lre[c] = a; lim[c] = b; hre[c] = d; him[c] = e;
            }
            int oo = o + 4 * hh;
            *(float4*)&S0[oo] = make_float4(lre[0], lre[1], lre[2], lre[3]);
            *(float4*)&S1[oo] = make_float4(lim[0], lim[1], lim[2], lim[3]);
            *(float4*)&S2[oo] = make_float4(hre[0], hre[1], hre[2], hre[3]);
            *(float4*)&S3[oo] = make_float4(him[0], him[1], him[2], him[3]);
        }
    }
    __syncthreads();
    phaseB<1024>(S0, S1, S2, S3, out, nxt, img, r0, c0, tid);
}

// ----------------------- levels 1..3 piece ---------------------------------
template<int H>
__device__ __forceinline__ void wave_piece(
    int u, const float* __restrict__ in, float* __restrict__ out,
    float* __restrict__ nxt, float* S0, float* S1, float* S2, float* S3, int tid)
{
    DECL_COEFS
    constexpr int hm   = H - 1;
    constexpr int TX   = (H / 2) / TCW;
    constexpr int TPI  = TX * ((H / 2) / TRW);
    const int img = u / TPI;
    const int rem = u & (TPI - 1);
    const int by  = rem / TX;
    const int bx  = rem & (TX - 1);
    const int r0  = by * TRW, c0 = bx * TCW;

    const float* in_re = in + (long)img * (2l * H * H);
    const float* in_im = in_re + (long)H * H;

    const int gr0  = 2 * r0 - 3;
    const int gcal = 2 * c0 - 4;
    for (int idx = tid; idx < RIW * (TCW / 4); idx += 256) {
        int ri = idx >> 3;
        int j  = idx & 7;
        int gr = (gr0 + ri) & hm;
        const float* pr = in_re + (long)gr * H;
        const float* pi = in_im + (long)gr * H;
        float x[16], y[16];
        #pragma unroll
        for (int k = 0; k < 4; k++) {
            int gc = (gcal + 8 * j + 4 * k) & hm;
            float4 v = *(const float4*)(pr + gc);
            x[4*k] = v.x; x[4*k+1] = v.y; x[4*k+2] = v.z; x[4*k+3] = v.w;
            float4 w = *(const float4*)(pi + gc);
            y[4*k] = w.x; y[4*k+1] = w.y; y[4*k+2] = w.z; y[4*k+3] = w.w;
        }
        float lre[4], lim[4], hre[4], him[4];
        #pragma unroll
        for (int c = 0; c < 4; c++) {
            float a = 0.f, b = 0.f, d = 0.f, e = 0.f;
            #pragma unroll
            for (int t = 0; t < 3; t++) {
                float xt = x[2*c + 1 + t], xs = x[2*c + 6 - t];
                float p = xt + xs, m = xt - xs;
                a += KLR[t] * p;  b += KLI[t] * p;
                d += KHR[t] * m;  e += KHI[t] * m;
                float yt = y[2*c + 1 + t], ys = y[2*c + 6 - t];
                float q = yt + ys, n = yt - ys;
                a -= KLI[t] * q;  b += KLR[t] * q;
                d -= KHI[t] * n;  e += KHR[t] * n;
            }
            lre[c] = a; lim[c] = b; hre[c] = d; him[c] = e;
        }
        int o = ri * PW + 4 * j;
        *(float4*)&S0[o] = make_float4(lre[0], lre[1], lre[2], lre[3]);
        *(float4*)&S1[o] = make_float4(lim[0], lim[1], lim[2], lim[3]);
        *(float4*)&S2[o] = make_float4(hre[0], hre[1], hre[2], hre[3]);
        *(float4*)&S3[o] = make_float4(him[0], him[1], him[2], him[3]);
    }
    __syncthreads();
    phaseB<H>(S0, S1, S2, S3, out, nxt, img, r0, c0, tid);
    __syncthreads();   // smem reused by next tile
}

// ---------------------- persistent kernel: L1..L3 ---------------------------
__global__ void __launch_bounds__(256, 5)
persist13(float* __restrict__ out,
          float* __restrict__ s01, float* __restrict__ s12,
          float* __restrict__ s23, float* __restrict__ s34)
{
    extern __shared__ float sm[];
    float* S0 = sm;
    float* S1 = sm + SARR;
    float* S2 = sm + 2 * SARR;
    float* S3 = sm + 3 * SARR;

    const int tid = threadIdx.x;
    const unsigned NB = gridDim.x;

    // L1: 24 x 128 tiles
    for (int u = blockIdx.x; u < 24 * 128; u += NB)
        wave_piece<512>(u, s01, out, s12, S0, S1, S2, S3, tid);
    grid_barrier(NB);
    // L2: 24 x 32 tiles
    for (int u = blockIdx.x; u < 24 * 32; u += NB)
        wave_piece<256>(u, s12, out, s23, S0, S1, S2, S3, tid);
    grid_barrier(NB);
    // L3: 24 x 8 tiles
    for (int u = blockIdx.x; u < 24 * 8; u += NB)
        wave_piece<128>(u, s23, out, s34, S0, S1, S2, S3, tid);
}

// =============================== levels 4..5 ================================
__device__ __forceinline__ void tail_level(
    const float* sre, const float* sim, int ps,
    float* dre, float* dim, int pd,
    float* I0, float* I1, float* I2, float* I3,
    float* o_re, float* o_im, int h, bool last, int tid)
{
    DECL_COEFS
    const int hm = h - 1, W = h + 5, half = h >> 1;
    for (int s0 = 0; s0 < half; s0 += 8) {
        for (int idx = tid; idx < 8 * W; idx += 512) {
            int rr = idx / W, jx = idx - rr * W;
            int col = (jx - 3) & hm;
            int r2 = 2 * (s0 + rr) - 3;
            float aLr = 0, aLi = 0, aHr = 0, aHi = 0;
            #pragma unroll
            for (int t = 0; t < 3; t++) {
                int ra = (r2 + t) & hm, rb = (r2 + 5 - t) & hm;
                float xa = sre[ra * ps + col], xb = sre[rb * ps + col];
                float va = sim[ra * ps + col], vb = sim[rb * ps + col];
                float p = xa + xb, m = xa - xb, q = va + vb, n = va - vb;
                aLr += KLR[t]*p;  aLr -= KLI[t]*q;
                aLi += KLI[t]*p;  aLi += KLR[t]*q;
                aHr += KHR[t]*m;  aHr -= KHI[t]*n;
                aHi += KHI[t]*m;  aHi += KHR[t]*n;
            }
            I0[rr * 136 + jx] = aLr; I1[rr * 136 + jx] = aLi;
            I2[rr * 136 + jx] = aHr; I3[rr * 136 + jx] = aHi;
        }
        __syncthreads();
        for (int idx = tid; idx < 8 * half; idx += 512) {
            int rr = idx / half, c = idx - rr * half;
            int r = s0 + rr;
            float LLr = 0, LLi = 0, LHr = 0, LHi = 0;
            float HLr = 0, HLi = 0, HHr = 0, HHi = 0;
            #pragma unroll
            for (int t = 0; t < 3; t++) {
                int j0 = 2 * c + t, j1 = 2 * c + 5 - t;
                float ar = I0[rr * 136 + j0], br = I0[rr * 136 + j1];
                float ai = I1[rr * 136 + j0], bi = I1[rr * 136 + j1];
                float p = ar + br, m = ar - br, q = ai + bi, n = ai - bi;
                LLr += KLR[t]*p;  LLr -= KLI[t]*q;
                LLi += KLI[t]*p;  LLi += KLR[t]*q;
                LHr += KHR[t]*m;  LHr -= KHI[t]*n;
                LHi += KHI[t]*m;  LHi += KHR[t]*n;
                ar = I2[rr * 136 + j0]; br = I2[rr * 136 + j1];
                ai = I3[rr * 136 + j0]; bi = I3[rr * 136 + j1];
                p = ar + br; m = ar - br; q = ai + bi; n = ai - bi;
                HLr += KLR[t]*p;  HLr -= KLI[t]*q;
                HLi += KLI[t]*p;  HLi += KLR[t]*q;
                HHr += KHR[t]*m;  HHr -= KHI[t]*n;
                HHi += KHI[t]*m;  HHi += KHR[t]*n;
            }
            o_re[r * 1024 + c + half]          = LHr;
            o_im[r * 1024 + c + half]          = LHi;
            o_re[(r + half) * 1024 + c]        = HLr;
            o_im[(r + half) * 1024 + c]        = HLi;
            o_re[(r + half) * 1024 + c + half] = HHr;
            o_im[(r + half) * 1024 + c + half] = HHi;
            if (last) {
                o_re[r * 1024 + c] = LLr;
                o_im[r * 1024 + c] = LLi;
            } else {
                dre[r * pd + c] = LLr;
                dim[r * pd + c] = LLi;
            }
        }
        __syncthreads();
    }
}

__global__ void __launch_bounds__(512)
wave_tail45(const float* __restrict__ in, float* __restrict__ out)
{
    extern __shared__ float sm[];
    constexpr int AP = 68, BP = 36;
    float* A_re = sm;
    float* A_im = A_re + 64 * AP;
    float* B_re = A_im + 64 * AP;
    float* B_im = B_re + 32 * BP;
    float* I0   = B_im + 32 * BP;
    float* I1   = I0 + 8 * 136;
    float* I2   = I1 + 8 * 136;
    float* I3   = I2 + 8 * 136;

    const int tid = threadIdx.x;
    const int img = blockIdx.x;

    const float* g_re = in + (long)img * 2l * 64 * 64;
    const float* g_im = g_re + 64 * 64;
    for (int idx = tid; idx < 64 * 16; idx += 512) {
        int rr = idx >> 4, c4 = (idx & 15) * 4;
        *(float4*)&A_re[rr * AP + c4] = *(const float4*)(g_re + rr * 64 + c4);
        *(float4*)&A_im[rr * AP + c4] = *(const float4*)(g_im + rr * 64 + c4);
    }
    __syncthreads();

    float* o_re = out + (long)img * 2l * 1024 * 1024;
    float* o_im = o_re + 1024 * 1024;

    tail_level(A_re, A_im, AP, B_re, B_im, BP, I0, I1, I2, I3,
               o_re, o_im, 64, false, tid);
    tail_level(B_re, B_im, BP, nullptr, nullptr, 0, I0, I1, I2, I3,
               o_re, o_im, 32, true, tid);
}

// ================================= launch ===================================
extern "C" void kernel_launch(void* const* d_in, const int* in_sizes, int n_in,
                              void* d_out, int out_size) {
    const float* images = (const float*)d_in[0];
    float* out = (float*)d_out;

    float *s01, *s12, *s23, *s34;
    cudaGetSymbolAddress((void**)&s01, g_s01);
    cudaGetSymbolAddress((void**)&s12, g_s12);
    cudaGetSymbolAddress((void**)&s23, g_s23);
    cudaGetSymbolAddress((void**)&s34, g_s34);

    const int bc = in_sizes[0] / (1024 * 1024);  // 24

    constexpr size_t SMEM_P = 4u * SARR * 4u;            // 20,736 B
    constexpr size_t SMT = (size_t)(2 * 64 * 68 + 2 * 32 * 36 + 4 * 8 * 136) * 4;
    cudaFuncSetAttribute(persist13,
                         cudaFuncAttributeMaxDynamicSharedMemorySize, SMEM_P);
    cudaFuncSetAttribute(wave_tail45,
                         cudaFuncAttributeMaxDynamicSharedMemorySize, SMT);

    int dev = 0;
    cudaGetDevice(&dev);
    int nsm = 148;
    cudaDeviceGetAttribute(&nsm, cudaDevAttrMultiProcessorCount, dev);
    int occ = 1;
    cudaOccupancyMaxActiveBlocksPerMultiprocessor(&occ, persist13, 256, SMEM_P);
    if (occ < 1) occ = 1;
    if (occ > 5) occ = 5;
    int nb = nsm * occ;

    // Level 0 (R11 kernel verbatim)
    {
        dim3 grid(512 / TCW, 512 / TRW, bc);
        wave0<<<grid, dim3(256)>>>(images, out, s01);
    }
    // Levels 1..3 in one persistent launch (small smem -> high co-residency)
    persist13<<<nb, 256, SMEM_P>>>(out, s01, s12, s23, s34);
    // Levels 4..5
    wave_tail45<<<bc, 512, SMT>>>(s34, out);
}

// round 17
// speedup vs baseline: 1.2235x; 1.0567x over previous
#include <cuda_runtime.h>

// ----------------------------------------------------------------------------
// Complex Daubechies wavelet forward decomposition, 6 levels. Round 17:
//  - R11 serial 5-launch chain (proven best structure).
//  - NEW: pair-interleaved smem layout for the phase-A -> phase-B handoff:
//    SA[row][pair] = float4{lo_re(c), lo_re(c+1), lo_im(c), lo_im(c+1)},
//    SB likewise for the hi-filtered pair. Phase B drops from 24 LDS.64 to
//    12 LDS.128 per thread (same bytes, half the LSU instructions).
//  - FFMA-immediate coefficients, details via __stcs, L0 input via __ldcs.
// ----------------------------------------------------------------------------

#define C_LR0 (-0.046875f)
#define C_LR1 ( 0.078125f)
#define C_LR2 ( 0.46875f)
#define C_LI0 (-0.0605153648f)
#define C_LI1 (-0.0605153648f)
#define C_LI2 ( 0.1210307296f)
#define C_HR0 (-0.046875f)
#define C_HR1 (-0.078125f)
#define C_HR2 ( 0.46875f)
#define C_HI0 ( 0.0605153648f)
#define C_HI1 (-0.0605153648f)
#define C_HI2 (-0.1210307296f)

#define DECL_COEFS \
    const float KLR[3] = {C_LR0, C_LR1, C_LR2}; \
    const float KLI[3] = {C_LI0, C_LI1, C_LI2}; \
    const float KHR[3] = {C_HR0, C_HR1, C_HR2}; \
    const float KHI[3] = {C_HI0, C_HI1, C_HI2};

// Ping-pong scratch for the LL chain.
__device__ float g_scr0[32u * 2u * 512u * 512u];
__device__ float g_scr1[32u * 2u * 512u * 512u];

// Tile constants: TR=16, TC=32. 36 intermediate rows; 16 col-pairs + pad.
#define TRW 16
#define TCW 32
#define RIW 36
#define PP  17          // pitch in float4 units (16 pairs + 1 pad)

// --------- shared phase-B body: pair-interleaved loads ----------------------
template<int H>
__device__ __forceinline__ void phaseB(
    const float4* SA, const float4* SB,
    float* __restrict__ out, float* __restrict__ nxt,
    int img, int r0, int c0, int tid)
{
    DECL_COEFS
    constexpr int half = H / 2;
    float* o_re = out + (long)img * (2l * 1024 * 1024);
    float* o_im = o_re + 1024 * 1024;
    float* n_re = nxt + (long)img * 2l * half * half;
    float* n_im = n_re + (long)half * half;

    int r  = tid >> 4;          // 16 rows x 16 pairs = 256 items exactly
    int cg = tid & 15;
    float LLr0=0, LLi0=0, LHr0=0, LHi0=0, HLr0=0, HLi0=0, HHr0=0, HHi0=0;
    float LLr1=0, LLi1=0, LHr1=0, LHi1=0, HLr1=0, HLi1=0, HHr1=0, HHi1=0;
    #pragma unroll
    for (int t = 0; t < 3; t++) {
        int ra = (2 * r + t) * PP + cg;
        int rb = (2 * r + 5 - t) * PP + cg;
        float4 aT = SA[ra], aS = SA[rb];    // {lre0,lre1,lim0,lim1}
        float4 bT = SB[ra], bS = SB[rb];    // {hre0,hre1,him0,him1}
        {   // column 0
            float p = aT.x + aS.x, m = aT.x - aS.x;
            float q = aT.z + aS.z, n = aT.z - aS.z;
            LLr0 += KLR[t]*p;  LLr0 -= KLI[t]*q;
            LLi0 += KLI[t]*p;  LLi0 += KLR[t]*q;
            HLr0 += KHR[t]*m;  HLr0 -= KHI[t]*n;
            HLi0 += KHI[t]*m;  HLi0 += KHR[t]*n;
            float p2 = bT.x + bS.x, m2 = bT.x - bS.x;
            float q2 = bT.z + bS.z, n2 = bT.z - bS.z;
            LHr0 += KLR[t]*p2; LHr0 -= KLI[t]*q2;
            LHi0 += KLI[t]*p2; LHi0 += KLR[t]*q2;
            HHr0 += KHR[t]*m2; HHr0 -= KHI[t]*n2;
            HHi0 += KHI[t]*m2; HHi0 += KHR[t]*n2;
        }
        {   // column 1
            float p = aT.y + aS.y, m = aT.y - aS.y;
            float q = aT.w + aS.w, n = aT.w - aS.w;
            LLr1 += KLR[t]*p;  LLr1 -= KLI[t]*q;
            LLi1 += KLI[t]*p;  LLi1 += KLR[t]*q;
            HLr1 += KHR[t]*m;  HLr1 -= KHI[t]*n;
            HLi1 += KHI[t]*m;  HLi1 += KHR[t]*n;
            float p2 = bT.y + bS.y, m2 = bT.y - bS.y;
            float q2 = bT.w + bS.w, n2 = bT.w - bS.w;
            LHr1 += KLR[t]*p2; LHr1 -= KLI[t]*q2;
            LHi1 += KLI[t]*p2; LHi1 += KLR[t]*q2;
            HHr1 += KHR[t]*m2; HHr1 -= KHI[t]*n2;
            HHi1 += KHI[t]*m2; HHi1 += KHR[t]*n2;
        }
    }
    int c2 = 2 * cg;
    int rl = r0 + r, rh = rl + half;
    int cl = c0 + c2, ch = cl + half;
    *(float2*)(n_re + (long)rl * half + cl) = make_float2(LLr0, LLr1);
    *(float2*)(n_im + (long)rl * half + cl) = make_float2(LLi0, LLi1);
    __stcs((float2*)(o_re + (long)rl * 1024 + ch), make_float2(LHr0, LHr1));
    __stcs((float2*)(o_im + (long)rl * 1024 + ch), make_float2(LHi0, LHi1));
    __stcs((float2*)(o_re + (long)rh * 1024 + cl), make_float2(HLr0, HLr1));
    __stcs((float2*)(o_im + (long)rh * 1024 + cl), make_float2(HLi0, HLi1));
    __stcs((float2*)(o_re + (long)rh * 1024 + ch), make_float2(HHr0, HHr1));
    __stcs((float2*)(o_im + (long)rh * 1024 + ch), make_float2(HHi0, HHi1));
}

// ======================= level-0 kernel (no imag input) =====================
__global__ void __launch_bounds__(256, 5)
wave0(const float* __restrict__ in, float* __restrict__ out,
      float* __restrict__ nxt)
{
    DECL_COEFS
    constexpr int H = 1024, hm = H - 1;
    __shared__ __align__(16) float4 SA[RIW * PP];
    __shared__ __align__(16) float4 SB[RIW * PP];

    const int tid = threadIdx.x;
    const int img = blockIdx.z;
    const int r0  = blockIdx.y * TRW;
    const int c0  = blockIdx.x * TCW;

    const float* in_re = in + (long)img * (1024l * 1024);
    const int gr0  = 2 * r0 - 3;
    const int gcal = 2 * c0 - 4;
    // 144 items: (row, 8-col group). Pairs 4j..4j+3.
    for (int idx = tid; idx < RIW * (TCW / 8); idx += 256) {
        int ri = idx >> 2;
        int j  = idx & 3;
        int gr = (gr0 + ri) & hm;
        const float* pr = in_re + (long)gr * H;
        float x[24];
        #pragma unroll
        for (int k = 0; k < 6; k++) {
            int gc = (gcal + 16 * j + 4 * k) & hm;
            float4 v = __ldcs((const float4*)(pr + gc));
            x[4*k] = v.x; x[4*k+1] = v.y; x[4*k+2] = v.z; x[4*k+3] = v.w;
        }
        int o = ri * PP + 4 * j;
        #pragma unroll
        for (int hh = 0; hh < 2; hh++) {
            float lre[4], lim[4], hre[4], him[4];
            #pragma unroll
            for (int c = 0; c < 4; c++) {
                int cc = c + 4 * hh;
                float a = 0.f, b = 0.f, d = 0.f, e = 0.f;
                #pragma unroll
                for (int t = 0; t < 3; t++) {
                    float xt = x[2*cc + 1 + t], xs = x[2*cc + 6 - t];
                    float p = xt + xs, m = xt - xs;
                    a += KLR[t] * p;  b += KLI[t] * p;
                    d += KHR[t] * m;  e += KHI[t] * m;
                }
                lre[c] = a; lim[c] = b; hre[c] = d; him[c] = e;
            }
            SA[o + 2*hh]     = make_float4(lre[0], lre[1], lim[0], lim[1]);
            SA[o + 2*hh + 1] = make_float4(lre[2], lre[3], lim[2], lim[3]);
            SB[o + 2*hh]     = make_float4(hre[0], hre[1], him[0], him[1]);
            SB[o + 2*hh + 1] = make_float4(hre[2], hre[3], him[2], him[3]);
        }
    }
    __syncthreads();
    phaseB<1024>(SA, SB, out, nxt, img, r0, c0, tid);
}

// ===================== levels 1..3 kernel (complex input) ===================
template<int H>
__global__ void __launch_bounds__(256, 5)
wave(const float* __restrict__ in, float* __restrict__ out,
     float* __restrict__ nxt)
{
    DECL_COEFS
    constexpr int hm = H - 1;
    __shared__ __align__(16) float4 SA[RIW * PP];
    __shared__ __align__(16) float4 SB[RIW * PP];

    const int tid = threadIdx.x;
    const int img = blockIdx.z;
    const int r0  = blockIdx.y * TRW;
    const int c0  = blockIdx.x * TCW;

    const float* in_re = in + (long)img * (2l * H * H);
    const float* in_im = in_re + (long)H * H;

    const int gr0  = 2 * r0 - 3;
    const int gcal = 2 * c0 - 4;
    // 288 items: (row, 4-col group). Pairs 2j, 2j+1.
    for (int idx = tid; idx < RIW * (TCW / 4); idx += 256) {
        int ri = idx >> 3;
        int j  = idx & 7;
        int gr = (gr0 + ri) & hm;
        const float* pr = in_re + (long)gr * H;
        const float* pi = in_im + (long)gr * H;
        float x[16], y[16];
        #pragma unroll
        for (int k = 0; k < 4; k++) {
            int gc = (gcal + 8 * j + 4 * k) & hm;
            float4 v = *(const float4*)(pr + gc);
            x[4*k] = v.x; x[4*k+1] = v.y; x[4*k+2] = v.z; x[4*k+3] = v.w;
            float4 w = *(const float4*)(pi + gc);
            y[4*k] = w.x; y[4*k+1] = w.y; y[4*k+2] = w.z; y[4*k+3] = w.w;
        }
        float lre[4], lim[4], hre[4], him[4];
        #pragma unroll
        for (int c = 0; c < 4; c++) {
            float a = 0.f, b = 0.f, d = 0.f, e = 0.f;
            #pragma unroll
            for (int t = 0; t < 3; t++) {
                float xt = x[2*c + 1 + t], xs = x[2*c + 6 - t];
                float p = xt + xs, m = xt - xs;
                a += KLR[t] * p;  b += KLI[t] * p;
                d += KHR[t] * m;  e += KHI[t] * m;
                float yt = y[2*c + 1 + t], ys = y[2*c + 6 - t];
                float q = yt + ys, n = yt - ys;
                a -= KLI[t] * q;  b += KLR[t] * q;
                d -= KHI[t] * n;  e += KHR[t] * n;
            }
            lre[c] = a; lim[c] = b; hre[c] = d; him[c] = e;
        }
        int o = ri * PP + 2 * j;
        SA[o]     = make_float4(lre[0], lre[1], lim[0], lim[1]);
        SA[o + 1] = make_float4(lre[2], lre[3], lim[2], lim[3]);
        SB[o]     = make_float4(hre[0], hre[1], him[0], him[1]);
        SB[o + 1] = make_float4(hre[2], hre[3], him[2], him[3]);
    }
    __syncthreads();
    phaseB<H>(SA, SB, out, nxt, img, r0, c0, tid);
}

// =============================== levels 4..5 ================================
__device__ __forceinline__ void tail_level(
    const float* sre, const float* sim, int ps,
    float* dre, float* dim, int pd,
    float* I0, float* I1, float* I2, float* I3,
    float* o_re, float* o_im, int h, bool last, int tid)
{
    DECL_COEFS
    const int hm = h - 1, W = h + 5, half = h >> 1;
    for (int s0 = 0; s0 < half; s0 += 8) {
        for (int idx = tid; idx < 8 * W; idx += 512) {
            int rr = idx / W, jx = idx - rr * W;
            int col = (jx - 3) & hm;
            int r2 = 2 * (s0 + rr) - 3;
            float aLr = 0, aLi = 0, aHr = 0, aHi = 0;
            #pragma unroll
            for (int t = 0; t < 3; t++) {
                int ra = (r2 + t) & hm, rb = (r2 + 5 - t) & hm;
                float xa = sre[ra * ps + col], xb = sre[rb * ps + col];
                float va = sim[ra * ps + col], vb = sim[rb * ps + col];
                float p = xa + xb, m = xa - xb, q = va + vb, n = va - vb;
                aLr += KLR[t]*p;  aLr -= KLI[t]*q;
                aLi += KLI[t]*p;  aLi += KLR[t]*q;
                aHr += KHR[t]*m;  aHr -= KHI[t]*n;
                aHi += KHI[t]*m;  aHi += KHR[t]*n;
            }
            I0[rr * 136 + jx] = aLr; I1[rr * 136 + jx] = aLi;
            I2[rr * 136 + jx] = aHr; I3[rr * 136 + jx] = aHi;
        }
        __syncthreads();
        for (int idx = tid; idx < 8 * half; idx += 512) {
            int rr = idx / half, c = idx - rr * half;
            int r = s0 + rr;
            float LLr = 0, LLi = 0, LHr = 0, LHi = 0;
            float HLr = 0, HLi = 0, HHr = 0, HHi = 0;
            #pragma unroll
            for (int t = 0; t < 3; t++) {
                int j0 = 2 * c + t, j1 = 2 * c + 5 - t;
                float ar = I0[rr * 136 + j0], br = I0[rr * 136 + j1];
                float ai = I1[rr * 136 + j0], bi = I1[rr * 136 + j1];
                float p = ar + br, m = ar - br, q = ai + bi, n = ai - bi;
                LLr += KLR[t]*p;  LLr -= KLI[t]*q;
                LLi += KLI[t]*p;  LLi += KLR[t]*q;
                LHr += KHR[t]*m;  LHr -= KHI[t]*n;
                LHi += KHI[t]*m;  LHi += KHR[t]*n;
                ar = I2[rr * 136 + j0]; br = I2[rr * 136 + j1];
                ai = I3[rr * 136 + j0]; bi = I3[rr * 136 + j1];
                p = ar + br; m = ar - br; q = ai + bi; n = ai - bi;
                HLr += KLR[t]*p;  HLr -= KLI[t]*q;
                HLi += KLI[t]*p;  HLi += KLR[t]*q;
                HHr += KHR[t]*m;  HHr -= KHI[t]*n;
                HHi += KHI[t]*m;  HHi += KHR[t]*n;
            }
            o_re[r * 1024 + c + half]          = LHr;
            o_im[r * 1024 + c + half]          = LHi;
            o_re[(r + half) * 1024 + c]        = HLr;
            o_im[(r + half) * 1024 + c]        = HLi;
            o_re[(r + half) * 1024 + c + half] = HHr;
            o_im[(r + half) * 1024 + c + half] = HHi;
            if (last) {
                o_re[r * 1024 + c] = LLr;
                o_im[r * 1024 + c] = LLi;
            } else {
                dre[r * pd + c] = LLr;
                dim[r * pd + c] = LLi;
            }
        }
        __syncthreads();
    }
}

__global__ void __launch_bounds__(512)
wave_tail45(const float* __restrict__ in, float* __restrict__ out)
{
    extern __shared__ float sm[];
    constexpr int AP = 68, BP = 36;
    float* A_re = sm;
    float* A_im = A_re + 64 * AP;
    float* B_re = A_im + 64 * AP;
    float* B_im = B_re + 32 * BP;
    float* I0   = B_im + 32 * BP;
    float* I1   = I0 + 8 * 136;
    float* I2   = I1 + 8 * 136;
    float* I3   = I2 + 8 * 136;

    const int tid = threadIdx.x;
    const int img = blockIdx.x;

    const float* g_re = in + (long)img * 2l * 64 * 64;
    const float* g_im = g_re + 64 * 64;
    for (int idx = tid; idx < 64 * 16; idx += 512) {
        int rr = idx >> 4, c4 = (idx & 15) * 4;
        *(float4*)&A_re[rr * AP + c4] = *(const float4*)(g_re + rr * 64 + c4);
        *(float4*)&A_im[rr * AP + c4] = *(const float4*)(g_im + rr * 64 + c4);
    }
    __syncthreads();

    float* o_re = out + (long)img * 2l * 1024 * 1024;
    float* o_im = o_re + 1024 * 1024;

    tail_level(A_re, A_im, AP, B_re, B_im, BP, I0, I1, I2, I3,
               o_re, o_im, 64, false, tid);
    tail_level(B_re, B_im, BP, nullptr, nullptr, 0, I0, I1, I2, I3,
               o_re, o_im, 32, true, tid);
}

// ================================= launch ===================================
extern "C" void kernel_launch(void* const* d_in, const int* in_sizes, int n_in,
                              void* d_out, int out_size) {
    const float* images = (const float*)d_in[0];
    float* out = (float*)d_out;

    float *scr0 = nullptr, *scr1 = nullptr;
    cudaGetSymbolAddress((void**)&scr0, g_scr0);
    cudaGetSymbolAddress((void**)&scr1, g_scr1);

    const int bc = in_sizes[0] / (1024 * 1024);  // B*C = 24

    constexpr size_t SMT = (size_t)(2 * 64 * 68 + 2 * 32 * 36 + 4 * 8 * 136) * 4;
    cudaFuncSetAttribute(wave_tail45,
                         cudaFuncAttributeMaxDynamicSharedMemorySize, SMT);

    dim3 blk(256);
    // Level 0: h=1024 (imag identically zero)
    {
        dim3 grid(512 / TCW, 512 / TRW, bc);
        wave0<<<grid, blk>>>(images, out, scr0);
    }
    // Level 1: h=512
    {
        dim3 grid(256 / TCW, 256 / TRW, bc);
        wave<512><<<grid, blk>>>(scr0, out, scr1);
    }
    // Level 2: h=256
    {
        dim3 grid(128 / TCW, 128 / TRW, bc);
        wave<256><<<grid, blk>>>(scr1, out, scr0);
    }
    // Level 3: h=128
    {
        dim3 grid(64 / TCW, 64 / TRW, bc);
        wave<128><<<grid, blk>>>(scr0, out, scr1);
    }
    // Levels 4..5 fused, one block per image
    wave_tail45<<<bc, 512, SMT>>>(scr1, out);
}